// round 4
// baseline (speedup 1.0000x reference)
#include <cuda_runtime.h>
#include <math.h>

#define BB 64
#define SS 256
#define II 512
#define HH 80
#define TT 600
#define CC 512
#define XD 592          /* HH + II */
#define KCAT 1104       /* XD + CC */
#define NCOLS 2048      /* gate-interleaved: 4 gates x 512 channels */
#define GRID 128
#define NTHR 256

// ---------------- device scratch ----------------
__device__ float g_xc[BB][XD];         // [frame 80 | prev 512]
__device__ float g_q[2][BB][CC];       // ping-pong GRU state
__device__ float g_wcat[NCOLS][KCAT];  // repacked, gate-interleaved GRU weights
__device__ float g_t1[BB][CC];
__device__ float g_dk[BB][168];
__device__ float g_energy[BB][SS];
__device__ float g_alpha[BB][SS];
__device__ unsigned g_bar, g_go;

__device__ __forceinline__ float sig_fast(float x) { return 1.f / (1.f + __expf(-x)); }
__device__ __forceinline__ float tanh_fast(float x) {
    float e = __expf(2.f * x);
    return 1.f - 2.f / (e + 1.f);
}
// packed f32x2 FMA (Blackwell): d = a*b + d  (2 independent fp32 FMAs)
__device__ __forceinline__ void fma2(unsigned long long& d, unsigned long long a,
                                     unsigned long long b) {
    asm("fma.rn.f32x2 %0, %1, %2, %0;" : "+l"(d) : "l"(a), "l"(b));
}

// grid barrier: release-arrive on counter, last arriver releases flag, acquire-poll
__device__ __forceinline__ void gsync(unsigned& gen) {
    gen++;
    __syncthreads();
    if (threadIdx.x == 0) {
        unsigned old;
        asm volatile("atom.add.release.gpu.global.u32 %0, [%1], 1;"
                     : "=r"(old) : "l"(&g_bar) : "memory");
        if (old == gen * GRID - 1u) {
            asm volatile("st.release.gpu.global.u32 [%0], %1;"
                         :: "l"(&g_go), "r"(gen) : "memory");
        } else {
            unsigned v;
            do {
                asm volatile("ld.acquire.gpu.global.u32 %0, [%1];"
                             : "=r"(v) : "l"(&g_go) : "memory");
            } while (v < gen);
        }
    }
    __syncthreads();
}

// ---------------- init: reset, zero state, gate-interleaved weight repack -----
__global__ void k_init(const float* __restrict__ wi, const float* __restrict__ wh) {
    int idx = blockIdx.x * blockDim.x + threadIdx.x;
    if (idx == 0) { g_bar = 0u; g_go = 0u; }
    if (idx < BB * CC) {
        int b = idx >> 9, c = idx & 511;
        g_q[0][b][c] = 0.f;
    }
    int stride = gridDim.x * blockDim.x;
    for (size_t i = idx; i < (size_t)NCOLS * KCAT; i += stride) {
        int n = (int)(i / KCAT), k = (int)(i % KCAT);
        int bq = n >> 4, v = n & 15, j = v >> 2, g = v & 3;
        int c = bq * 4 + j;
        float val;
        if (g == 0)      val = (k < XD) ? wi[(size_t)c * XD + k] : wh[(size_t)c * CC + (k - XD)];
        else if (g == 1) val = (k < XD) ? wi[(size_t)(512 + c) * XD + k] : wh[(size_t)(512 + c) * CC + (k - XD)];
        else if (g == 2) val = (k < XD) ? wi[(size_t)(1024 + c) * XD + k] : 0.f;
        else             val = (k < XD) ? 0.f : wh[(size_t)(1024 + c) * CC + (k - XD)];
        g_wcat[n][k] = val;
    }
}

// ---------------- the persistent kernel ----------------
__global__ void __launch_bounds__(NTHR)
k_persist(const float* __restrict__ enc, const float* __restrict__ gt,
          const float* __restrict__ mask,
          const float* __restrict__ bi, const float* __restrict__ bh,
          const float* __restrict__ w1, const float* __restrict__ b1,
          const float* __restrict__ w2,
          const float* __restrict__ lw, const float* __restrict__ lp,
          const float* __restrict__ dw, const float* __restrict__ db,
          const float* __restrict__ aw, const float* __restrict__ prior,
          float* __restrict__ out) {
    __shared__ __align__(16) float sm[9600];
    unsigned gen = 0;
    int bid = blockIdx.x, tid = threadIdx.x;
    int lane = tid & 31, wrp = tid >> 5;

    for (int t = 0;; t++) {
        int cur = t & 1, nxt = cur ^ 1;

        // ========== Phase A: softmax(energy) -> alpha -> out row t-1 -> prev ==
        {
            int b = bid >> 1, half = bid & 1;
            float* s_alpha = sm;         // 256
            float* s_red   = sm + 256;   // 8
            float* s_part  = sm + 272;   // 1024, 16B aligned

            float a;
            if (t == 0) {
                a = (tid == 0) ? 1.f : 0.f;
            } else {
                float e = __ldcg(&g_energy[b][tid]);
                float m = e;
                #pragma unroll
                for (int o = 16; o; o >>= 1) m = fmaxf(m, __shfl_xor_sync(0xffffffffu, m, o));
                if (lane == 0) s_red[wrp] = m;
                __syncthreads();
                float bm = s_red[0];
                #pragma unroll
                for (int i = 1; i < 8; i++) bm = fmaxf(bm, s_red[i]);
                float p = __expf(e - bm);
                float ws = p;
                #pragma unroll
                for (int o = 16; o; o >>= 1) ws += __shfl_xor_sync(0xffffffffu, ws, o);
                __syncthreads();
                if (lane == 0) s_red[wrp] = ws;
                __syncthreads();
                float tot = 0.f;
                #pragma unroll
                for (int i = 0; i < 8; i++) tot += s_red[i];
                a = p / tot;
                if (half == 0) out[((size_t)b * TT + (t - 1)) * SS + tid] = a;
            }
            s_alpha[tid] = a;
            if (half == 0) g_alpha[b][tid] = a;
            __syncthreads();

            if (t == TT) break;

            if (half == 0 && tid < HH)
                g_xc[b][tid] = gt[((size_t)b * TT + t) * HH + tid];

            int cs = tid & 63, sl = tid >> 6;
            int c = half * 256 + cs * 4;
            const float* ep = enc + (size_t)b * SS * II + c;
            float4 acc = make_float4(0.f, 0.f, 0.f, 0.f);
            #pragma unroll 8
            for (int s = sl * 64; s < sl * 64 + 64; s++) {
                float av = s_alpha[s];
                float4 ev = *(const float4*)&ep[(size_t)s * II];
                acc.x = fmaf(av, ev.x, acc.x);
                acc.y = fmaf(av, ev.y, acc.y);
                acc.z = fmaf(av, ev.z, acc.z);
                acc.w = fmaf(av, ev.w, acc.w);
            }
            *(float4*)&s_part[(sl * 64 + cs) * 4] = acc;
            __syncthreads();
            if (tid < 64) {
                float4 r = *(const float4*)&s_part[tid * 4];
                #pragma unroll
                for (int ks = 1; ks < 4; ks++) {
                    float4 v = *(const float4*)&s_part[(ks * 64 + tid) * 4];
                    r.x += v.x; r.y += v.y; r.z += v.z; r.w += v.w;
                }
                *(float4*)&g_xc[b][HH + half * 256 + tid * 4] = r;
            }
        }
        gsync(gen);

        // ========== Phase B: GRU GEMM (f32x2) + fused gates -> g_q[nxt] =======
        {
            int col0 = bid * 16;
            float*  sxs = sm;                      // 2 x 48*68 = 6528
            float2* sws = (float2*)&sm[6528];      // 2 x 48*16 float2 = 3072 floats
            int ks = tid >> 6, r = tid & 63, ty = r >> 2, tx = r & 3;
            unsigned long long a2[2][4] = {{0ull,0ull,0ull,0ull},{0ull,0ull,0ull,0ull}};

            float rx[12], rw[3];
            // prefetch chunk 0
            #pragma unroll
            for (int it = 0; it < 12; it++) {
                int idx = tid + it * 256;
                int rr = idx / 48, kk = idx - rr * 48;
                rx[it] = (kk < XD) ? __ldcg(&g_xc[rr][kk]) : __ldcg(&g_q[cur][rr][kk - XD]);
            }
            #pragma unroll
            for (int it = 0; it < 3; it++) {
                int idx = tid + it * 256;
                int rr = idx / 48, kk = idx - rr * 48;
                rw[it] = g_wcat[col0 + rr][kk];
            }
            for (int ch = 0; ch < 23; ch++) {
                int buf = ch & 1;
                float*  xb = sxs + buf * 3264;
                float2* wb = sws + buf * 768;
                #pragma unroll
                for (int it = 0; it < 12; it++) {
                    int idx = tid + it * 256;
                    int rr = idx / 48, kk = idx - rr * 48;
                    xb[kk * 68 + rr] = rx[it];
                }
                #pragma unroll
                for (int it = 0; it < 3; it++) {
                    int idx = tid + it * 256;
                    int rr = idx / 48, kk = idx - rr * 48;
                    wb[kk * 16 + rr] = make_float2(rw[it], rw[it]);
                }
                __syncthreads();
                if (ch + 1 < 23) {
                    int kc = (ch + 1) * 48;
                    #pragma unroll
                    for (int it = 0; it < 12; it++) {
                        int idx = tid + it * 256;
                        int rr = idx / 48, kk = kc + (idx - rr * 48);
                        rx[it] = (kk < XD) ? __ldcg(&g_xc[rr][kk]) : __ldcg(&g_q[cur][rr][kk - XD]);
                    }
                    #pragma unroll
                    for (int it = 0; it < 3; it++) {
                        int idx = tid + it * 256;
                        int rr = idx / 48, kk = idx - rr * 48;
                        rw[it] = g_wcat[col0 + rr][kc + kk];
                    }
                }
                #pragma unroll
                for (int kk = 0; kk < 12; kk++) {
                    int k = ks * 12 + kk;
                    ulonglong2 xp = *(const ulonglong2*)&xb[k * 68 + ty * 4];
                    const ulonglong2* wrow = (const ulonglong2*)&wb[k * 16 + tx * 4];
                    ulonglong2 wp0 = wrow[0];
                    ulonglong2 wp1 = wrow[1];
                    fma2(a2[0][0], xp.x, wp0.x); fma2(a2[1][0], xp.y, wp0.x);
                    fma2(a2[0][1], xp.x, wp0.y); fma2(a2[1][1], xp.y, wp0.y);
                    fma2(a2[0][2], xp.x, wp1.x); fma2(a2[1][2], xp.y, wp1.x);
                    fma2(a2[0][3], xp.x, wp1.y); fma2(a2[1][3], xp.y, wp1.y);
                }
            }
            __syncthreads();
            float* red = sm;  // 4*64*18 = 4608
            int base = (ks * 64 + r) * 18;
            #pragma unroll
            for (int g = 0; g < 4; g++) {
                *(unsigned long long*)&red[base + g * 4 + 0] = a2[0][g];
                *(unsigned long long*)&red[base + g * 4 + 2] = a2[1][g];
            }
            __syncthreads();
            {
                int b = tid & 63, j = tid >> 6;
                int rr = (b >> 2) * 4 + j, i = b & 3;
                float G[4];
                #pragma unroll
                for (int g = 0; g < 4; g++)
                    G[g] = red[(0 * 64 + rr) * 18 + g * 4 + i]
                         + red[(1 * 64 + rr) * 18 + g * 4 + i]
                         + red[(2 * 64 + rr) * 18 + g * 4 + i]
                         + red[(3 * 64 + rr) * 18 + g * 4 + i];
                int c = bid * 4 + j;
                float rg = sig_fast(G[0] + bi[c] + bh[c]);
                float zg = sig_fast(G[1] + bi[512 + c] + bh[512 + c]);
                float ng = tanh_fast(G[2] + bi[1024 + c] + rg * (G[3] + bh[1024 + c]));
                float st = __ldcg(&g_q[cur][b][c]);
                g_q[nxt][b][c] = (1.f - zg) * ng + zg * st;
            }
        }
        gsync(gen);

        // ========== Phase D: t1 = tanh(q_new @ W1^T + b1), 4 cols/block =======
        {
            int col0 = bid * 4;
            float* sxs = sm;            // 2 x 64*68 = 8704
            float* sws = sm + 8704;     // 2 x 64*4  = 512
            int ks = tid >> 6, r = tid & 63, ty = r >> 2, tx = r & 3;
            float a0 = 0, a1 = 0, a2_ = 0, a3 = 0;

            float px[16], pw;
            #pragma unroll
            for (int it = 0; it < 16; it++) {
                int idx = tid + it * 256;
                px[it] = __ldcg(&g_q[nxt][idx >> 6][idx & 63]);
            }
            pw = w1[(size_t)(col0 + (tid & 3)) * CC + (tid >> 2)];
            for (int ch = 0; ch < 8; ch++) {
                int buf = ch & 1;
                float* xb = sxs + buf * 4352;
                float* wb = sws + buf * 256;
                #pragma unroll
                for (int it = 0; it < 16; it++) {
                    int idx = tid + it * 256;
                    xb[(idx & 63) * 68 + (idx >> 6)] = px[it];
                }
                wb[(tid >> 2) * 4 + (tid & 3)] = pw;
                __syncthreads();
                if (ch + 1 < 8) {
                    int kc = (ch + 1) * 64;
                    #pragma unroll
                    for (int it = 0; it < 16; it++) {
                        int idx = tid + it * 256;
                        px[it] = __ldcg(&g_q[nxt][idx >> 6][kc + (idx & 63)]);
                    }
                    pw = w1[(size_t)(col0 + (tid & 3)) * CC + kc + (tid >> 2)];
                }
                #pragma unroll
                for (int kk = 0; kk < 16; kk++) {
                    int k = ks * 16 + kk;
                    float4 xv = *(const float4*)&xb[k * 68 + ty * 4];
                    float w = wb[k * 4 + tx];
                    a0 = fmaf(xv.x, w, a0); a1 = fmaf(xv.y, w, a1);
                    a2_ = fmaf(xv.z, w, a2_); a3 = fmaf(xv.w, w, a3);
                }
            }
            __syncthreads();
            float* red = sm;  // 4*64*5 = 1280
            int base = (ks * 64 + r) * 5;
            red[base] = a0; red[base + 1] = a1; red[base + 2] = a2_; red[base + 3] = a3;
            __syncthreads();
            {
                int rr = tid >> 2, i = tid & 3;
                float v = red[rr * 5 + i] + red[(64 + rr) * 5 + i]
                        + red[(128 + rr) * 5 + i] + red[(192 + rr) * 5 + i];
                int b = (rr >> 2) * 4 + i, c = col0 + (rr & 3);
                g_t1[b][c] = tanh_fast(v + b1[c]);
            }
        }
        gsync(gen);

        // ========== Phase E: dk = t1 @ W2^T, 2 cols/block (84 active) =========
        {
            int col0 = bid * 2;
            bool active = (col0 < 168);
            if (active) {
                float* sxs = sm;
                float* sws = sm + 8704;   // 2 x 64*2 = 256
                int ks = tid >> 6, r = tid & 63, ty = r >> 1, tx = r & 1;
                float a0 = 0, a1 = 0;

                float px[16], pw;
                #pragma unroll
                for (int it = 0; it < 16; it++) {
                    int idx = tid + it * 256;
                    px[it] = __ldcg(&g_t1[idx >> 6][idx & 63]);
                }
                pw = (tid < 128) ? w2[(size_t)(col0 + (tid & 1)) * CC + (tid >> 1)] : 0.f;
                for (int ch = 0; ch < 8; ch++) {
                    int buf = ch & 1;
                    float* xb = sxs + buf * 4352;
                    float* wb = sws + buf * 128;
                    #pragma unroll
                    for (int it = 0; it < 16; it++) {
                        int idx = tid + it * 256;
                        xb[(idx & 63) * 68 + (idx >> 6)] = px[it];
                    }
                    if (tid < 128) wb[(tid >> 1) * 2 + (tid & 1)] = pw;
                    __syncthreads();
                    if (ch + 1 < 8) {
                        int kc = (ch + 1) * 64;
                        #pragma unroll
                        for (int it = 0; it < 16; it++) {
                            int idx = tid + it * 256;
                            px[it] = __ldcg(&g_t1[idx >> 6][kc + (idx & 63)]);
                        }
                        if (tid < 128) pw = w2[(size_t)(col0 + (tid & 1)) * CC + kc + (tid >> 1)];
                    }
                    #pragma unroll
                    for (int kk = 0; kk < 16; kk++) {
                        int k = ks * 16 + kk;
                        float2 xv = *(const float2*)&xb[k * 68 + ty * 2];
                        float w = wb[k * 2 + tx];
                        a0 = fmaf(xv.x, w, a0); a1 = fmaf(xv.y, w, a1);
                    }
                }
                __syncthreads();
                float* red = sm;  // 4*64*3 = 768
                int base = (ks * 64 + r) * 3;
                red[base] = a0; red[base + 1] = a1;
                __syncthreads();
                if (tid < 128) {
                    int rr = tid >> 1, i = tid & 1;
                    float v = red[rr * 3 + i] + red[(64 + rr) * 3 + i]
                            + red[(128 + rr) * 3 + i] + red[(192 + rr) * 3 + i];
                    int b = (rr >> 1) * 2 + i, c = col0 + (rr & 1);
                    g_dk[b][c] = v;
                }
            }
        }
        gsync(gen);

        // ========== Phase F: convs + score (f32x2) + energy ====================
        {
            int b = bid >> 1, shalf = bid & 1, s0 = shalf * 128;
            float* s_a   = sm;          // 148
            float* s_lw  = sm + 148;    // 168
            float* s_dkk = sm + 316;    // 168
            float* s_ft  = sm + 484;    // 128*16 = 2048 (16B aligned)
            float* s_pri = sm + 2532;   // 128
            float* s_en  = sm + 2660;   // 8*128 = 1024

            if (tid < 148) {
                int s = s0 - 10 + tid;
                s_a[tid] = (s >= 0 && s < SS) ? __ldcg(&g_alpha[b][s]) : 0.f;
            }
            if (tid < 168) {
                s_lw[tid]  = lw[tid];
                s_dkk[tid] = __ldcg(&g_dk[b][tid]);
            }
            __syncthreads();

            #pragma unroll
            for (int it = 0; it < 8; it++) {
                int idx = tid + it * 256;
                int l = idx & 15, si = idx >> 4;
                const float* wv = (l < 8) ? &s_lw[l * 21] : &s_dkk[(l - 8) * 21];
                float a = 0.f;
                #pragma unroll
                for (int k = 0; k < 21; k++) a = fmaf(s_a[si + k], wv[k], a);
                s_ft[si * 16 + l] = a;
            }
            if (tid < 128) {
                float a = 0.f;
                #pragma unroll
                for (int k = 0; k < 11; k++) a = fmaf(s_a[tid + k], prior[k], a);
                s_pri[tid] = a;
            }
            __syncthreads();

            int c = tid;
            ulonglong2 lpa = *(const ulonglong2*)&lp[c * 8];
            ulonglong2 lpb = *(const ulonglong2*)&lp[c * 8 + 4];
            ulonglong2 dwa = *(const ulonglong2*)&dw[c * 8];
            ulonglong2 dwb = *(const ulonglong2*)&dw[c * 8 + 4];
            float dbc = db[c], awc = aw[c];
            unsigned long long dbc2 = (unsigned long long)__float_as_uint(dbc);
            for (int si = 0; si < 128; si++) {
                const ulonglong2* fp = (const ulonglong2*)&s_ft[si * 16];
                ulonglong2 f01 = fp[0], f23 = fp[1];
                unsigned long long acc = dbc2;
                fma2(acc, lpa.x, f01.x); fma2(acc, lpa.y, f01.y);
                fma2(acc, lpb.x, f23.x); fma2(acc, lpb.y, f23.y);
                const ulonglong2* fq = (const ulonglong2*)&s_ft[si * 16 + 8];
                ulonglong2 f45 = fq[0], f67 = fq[1];
                fma2(acc, dwa.x, f45.x); fma2(acc, dwa.y, f45.y);
                fma2(acc, dwb.x, f67.x); fma2(acc, dwb.y, f67.y);
                float sc = __uint_as_float((unsigned)acc) +
                           __uint_as_float((unsigned)(acc >> 32));
                float v = awc * tanh_fast(sc);
                #pragma unroll
                for (int o = 16; o; o >>= 1) v += __shfl_xor_sync(0xffffffffu, v, o);
                if (lane == 0) s_en[wrp * 128 + si] = v;
            }
            __syncthreads();
            if (tid < 128) {
                float e = 0.f;
                #pragma unroll
                for (int i = 0; i < 8; i++) e += s_en[i * 128 + tid];
                e += __logf(s_pri[tid] + 1e-5f);
                int s = s0 + tid;
                e = (mask[b * SS + s] > 0.f) ? e : -INFINITY;
                g_energy[b][s] = e;
            }
        }
        gsync(gen);
    }
}

extern "C" void kernel_launch(void* const* d_in, const int* in_sizes, int n_in,
                              void* d_out, int out_size) {
    const float* enc   = (const float*)d_in[0];
    const float* mask  = (const float*)d_in[1];
    const float* gt    = (const float*)d_in[2];
    const float* wi    = (const float*)d_in[3];
    const float* wh    = (const float*)d_in[4];
    const float* bi    = (const float*)d_in[5];
    const float* bh    = (const float*)d_in[6];
    const float* lw    = (const float*)d_in[7];
    const float* lp    = (const float*)d_in[8];
    const float* w1    = (const float*)d_in[9];
    const float* b1    = (const float*)d_in[10];
    const float* w2    = (const float*)d_in[11];
    const float* dw    = (const float*)d_in[12];
    const float* db    = (const float*)d_in[13];
    const float* aw    = (const float*)d_in[14];
    const float* prior = (const float*)d_in[15];
    float* out = (float*)d_out;

    k_init<<<512, 256>>>(wi, wh);
    k_persist<<<GRID, NTHR>>>(enc, gt, mask, bi, bh, w1, b1, w2,
                              lw, lp, dw, db, aw, prior, out);
}